// round 4
// baseline (speedup 1.0000x reference)
#include <cuda_runtime.h>

#define N_NODES_MAX 100000
#define N_EDGES_MAX 1600000
#define D 128

// ---------------- scratch (static device globals; no runtime allocation) ---
// NOTE: these are referenced ONLY inside device code. Passing a __device__
// symbol as a kernel argument from host passes the host shadow address, and
// on GB300 (ATS) the GPU happily writes host memory -> silent wrong answers.
__device__ float g_support[(size_t)N_NODES_MAX * D];   // X @ W
__device__ int2  g_cv[N_EDGES_MAX];                    // CSR payload: (col, val-bits)
__device__ int   g_counts[N_NODES_MAX];                // per-row edge count
__device__ int   g_cur[N_NODES_MAX];                   // scatter cursors
__device__ int   g_incl[N_NODES_MAX];                  // block-local inclusive scan
__device__ int   g_rowstart[N_NODES_MAX];              // exclusive scan (CSR row ptr)
__device__ int   g_bsum[512];                          // per-block scan sums

// ---------------- CSR build ------------------------------------------------
__global__ void k_init_counts(int n) {
    int i = blockIdx.x * blockDim.x + threadIdx.x;
    if (i < n) { g_counts[i] = 0; g_cur[i] = 0; }
}

// edge indices are int32 (JAX x64-disabled downcasts the requested int64)
__global__ void k_hist(const int* __restrict__ row, int e) {
    int i = blockIdx.x * blockDim.x + threadIdx.x;
    if (i < e) atomicAdd(&g_counts[row[i]], 1);
}

#define SCAN_B 512
__global__ void k_scan1(int n) {   // per-block inclusive scan of g_counts
    __shared__ int s[SCAN_B];
    int tid = threadIdx.x;
    int i = blockIdx.x * SCAN_B + tid;
    int v = (i < n) ? g_counts[i] : 0;
    s[tid] = v;
    __syncthreads();
    #pragma unroll
    for (int off = 1; off < SCAN_B; off <<= 1) {
        int t = 0;
        if (tid >= off) t = s[tid - off];
        __syncthreads();
        if (tid >= off) s[tid] += t;
        __syncthreads();
    }
    if (i < n) g_incl[i] = s[tid];
    if (tid == SCAN_B - 1) g_bsum[blockIdx.x] = s[tid];
}

__global__ void k_scan2(int nb) {  // exclusive scan of block sums (single block)
    __shared__ int s[SCAN_B];
    int tid = threadIdx.x;
    int v = (tid < nb) ? g_bsum[tid] : 0;
    s[tid] = v;
    __syncthreads();
    #pragma unroll
    for (int off = 1; off < SCAN_B; off <<= 1) {
        int t = 0;
        if (tid >= off) t = s[tid - off];
        __syncthreads();
        if (tid >= off) s[tid] += t;
        __syncthreads();
    }
    if (tid < nb) g_bsum[tid] = s[tid] - v;   // exclusive
}

__global__ void k_scan3(int n) {   // rowstart[i] = exclusive scan of counts
    int i = blockIdx.x * blockDim.x + threadIdx.x;
    if (i < n) g_rowstart[i] = g_incl[i] - g_counts[i] + g_bsum[i / SCAN_B];
}

__global__ void k_scatter(const int* __restrict__ row,
                          const int* __restrict__ col,
                          const float* __restrict__ val, int e) {
    int i = blockIdx.x * blockDim.x + threadIdx.x;
    if (i < e) {
        int r = row[i];
        int pos = g_rowstart[r] + atomicAdd(&g_cur[r], 1);
        g_cv[pos] = make_int2(col[i], __float_as_int(val[i]));
    }
}

// ---------------- dense GEMM: g_support = X @ W  (fp32) --------------------
// BM=64 rows/block, BN=D=128 cols, BK=16, 256 threads, 8x4 micro-tile/thread
#define BM 64
#define BK 16
#define PAD_BM 68

__global__ __launch_bounds__(256) void k_gemm(const float* __restrict__ x,
                                              const float* __restrict__ w, int n) {
    __shared__ __align__(16) float As[BK][PAD_BM];   // transposed x tile
    __shared__ __align__(16) float Bs[BK][D];
    int tid  = threadIdx.x;
    int row0 = blockIdx.x * BM;

    int lr = tid >> 2;           // 0..63  x-tile row
    int lk = (tid & 3) << 2;     // 0,4,8,12 k offset
    int wr = tid >> 5;           // 0..7   W-tile row pair
    int wc = (tid & 31) << 2;    // W col offset
    int tx = tid & 31;           // out col group: tx*4
    int ty = tid >> 5;           // out row group: ty*8

    float acc[8][4];
    #pragma unroll
    for (int i = 0; i < 8; i++)
        #pragma unroll
        for (int j = 0; j < 4; j++) acc[i][j] = 0.0f;

    for (int k0 = 0; k0 < D; k0 += BK) {
        int gr = row0 + lr;
        float4 xv = make_float4(0.f, 0.f, 0.f, 0.f);
        if (gr < n) xv = *(const float4*)(x + (size_t)gr * D + k0 + lk);
        As[lk + 0][lr] = xv.x;
        As[lk + 1][lr] = xv.y;
        As[lk + 2][lr] = xv.z;
        As[lk + 3][lr] = xv.w;
        *(float4*)&Bs[wr][wc]     = *(const float4*)(w + (size_t)(k0 + wr) * D + wc);
        *(float4*)&Bs[wr + 8][wc] = *(const float4*)(w + (size_t)(k0 + wr + 8) * D + wc);
        __syncthreads();

        #pragma unroll
        for (int kk = 0; kk < BK; kk++) {
            float4 b  = *(const float4*)&Bs[kk][tx << 2];
            float4 a0 = *(const float4*)&As[kk][ty << 3];
            float4 a1 = *(const float4*)&As[kk][(ty << 3) + 4];
            float ar[8] = {a0.x, a0.y, a0.z, a0.w, a1.x, a1.y, a1.z, a1.w};
            #pragma unroll
            for (int i = 0; i < 8; i++) {
                acc[i][0] = fmaf(ar[i], b.x, acc[i][0]);
                acc[i][1] = fmaf(ar[i], b.y, acc[i][1]);
                acc[i][2] = fmaf(ar[i], b.z, acc[i][2]);
                acc[i][3] = fmaf(ar[i], b.w, acc[i][3]);
            }
        }
        __syncthreads();
    }

    #pragma unroll
    for (int i = 0; i < 8; i++) {
        int gr = row0 + (ty << 3) + i;
        if (gr < n) {
            float4 o = make_float4(acc[i][0], acc[i][1], acc[i][2], acc[i][3]);
            *(float4*)(g_support + (size_t)gr * D + (tx << 2)) = o;
        }
    }
}

// ---------------- gather: out[r] = bias + sum val * support[col] ------------
// one warp per row; lane owns 4 output columns (float4)
__global__ __launch_bounds__(256) void k_gather(const float* __restrict__ bias,
                                                float* __restrict__ out, int n) {
    int w    = (blockIdx.x * blockDim.x + threadIdx.x) >> 5;
    int lane = threadIdx.x & 31;
    if (w >= n) return;
    int start = g_rowstart[w];
    int len   = g_counts[w];
    int c4    = lane << 2;

    float4 acc = *(const float4*)(bias + c4);

    int i = 0;
    for (; i + 2 <= len; i += 2) {
        int2 cv0 = g_cv[start + i];
        int2 cv1 = g_cv[start + i + 1];
        float4 s0 = *(const float4*)(g_support + (size_t)cv0.x * D + c4);
        float4 s1 = *(const float4*)(g_support + (size_t)cv1.x * D + c4);
        float v0 = __int_as_float(cv0.y);
        float v1 = __int_as_float(cv1.y);
        acc.x = fmaf(v0, s0.x, acc.x);
        acc.y = fmaf(v0, s0.y, acc.y);
        acc.z = fmaf(v0, s0.z, acc.z);
        acc.w = fmaf(v0, s0.w, acc.w);
        acc.x = fmaf(v1, s1.x, acc.x);
        acc.y = fmaf(v1, s1.y, acc.y);
        acc.z = fmaf(v1, s1.z, acc.z);
        acc.w = fmaf(v1, s1.w, acc.w);
    }
    if (i < len) {
        int2 cv = g_cv[start + i];
        float4 s = *(const float4*)(g_support + (size_t)cv.x * D + c4);
        float v = __int_as_float(cv.y);
        acc.x = fmaf(v, s.x, acc.x);
        acc.y = fmaf(v, s.y, acc.y);
        acc.z = fmaf(v, s.z, acc.z);
        acc.w = fmaf(v, s.w, acc.w);
    }
    *(float4*)(out + (size_t)w * D + c4) = acc;
}

// ---------------- launch ----------------------------------------------------
extern "C" void kernel_launch(void* const* d_in, const int* in_sizes, int n_in,
                              void* d_out, int out_size) {
    const float* x    = (const float*)d_in[0];
    const int*   erow = (const int*)d_in[1];
    const int*   ecol = (const int*)d_in[2];
    const float* eval = (const float*)d_in[3];
    const float* wgt  = (const float*)d_in[4];
    const float* bias = (const float*)d_in[5];
    float* out = (float*)d_out;

    int n = in_sizes[0] / D;      // 100000
    int e = in_sizes[1];          // 1600000
    (void)n_in; (void)out_size;

    int nb_nodes = (n + 255) / 256;
    int nb_edges = (e + 255) / 256;
    int nb_scan  = (n + SCAN_B - 1) / SCAN_B;

    // dense GEMM (independent of CSR build)
    k_gemm<<<(n + BM - 1) / BM, 256>>>(x, wgt, n);

    // CSR build
    k_init_counts<<<nb_nodes, 256>>>(n);
    k_hist<<<nb_edges, 256>>>(erow, e);
    k_scan1<<<nb_scan, SCAN_B>>>(n);
    k_scan2<<<1, SCAN_B>>>(nb_scan);
    k_scan3<<<nb_nodes, 256>>>(n);
    k_scatter<<<nb_edges, 256>>>(erow, ecol, eval, e);

    // atomic-free row gather
    k_gather<<<(n * 32 + 255) / 256, 256>>>(bias, out, n);
}